// round 1
// baseline (speedup 1.0000x reference)
#include <cuda_runtime.h>
#include <cstdint>

// Problem dims (fixed by the dataset)
#define T_DIM 128
#define B_DIM 64
#define H_DIM 1024
#define M_DIM (T_DIM * B_DIM)   // 8192 rows for both GEMMs

// Scratch (allocation-free rule: __device__ globals)
__device__ float g_xproj[(size_t)M_DIM * H_DIM];  // 32 MB
__device__ float g_spk[(size_t)M_DIM * H_DIM];    // 32 MB

// ----------------------------------------------------------------------------
// SGEMM (NT): C[M,N] = A[M,K] * B[N,K]^T, A and B both row-major with K
// contiguous (so A and B tiles load with the identical pattern).
// BM=128, BN=128, BK=16, 256 threads, 8x8 register microtile.
// ----------------------------------------------------------------------------
template<int BM, int BN, int BK, int TM, int TN>
__global__ void __launch_bounds__(256, 1)
sgemm_nt(const float* __restrict__ A,
         const float* __restrict__ Bm,
         float* __restrict__ C,
         int M, int N, int K)
{
    __shared__ float As[BK][BM];   // transposed: [k][m]
    __shared__ float Bs[BK][BN];   // transposed: [k][n]

    const int tid  = threadIdx.x;
    const int tcol = tid % (BN / TN);  // 0..15
    const int trow = tid / (BN / TN);  // 0..15
    const int m0 = blockIdx.y * BM;
    const int n0 = blockIdx.x * BN;

    // Global->smem: each thread loads 2 float4 per operand per K-tile.
    // Tile is BM(=128) rows x BK(=16) cols; as float4: 128 x 4. 256 threads
    // cover 64 rows per pass -> 2 passes.
    const int ldRow = tid / (BK / 4);        // 0..63
    const int ldC   = (tid % (BK / 4)) * 4;  // 0,4,8,12

    float acc[TM][TN];
    #pragma unroll
    for (int i = 0; i < TM; i++)
        #pragma unroll
        for (int j = 0; j < TN; j++)
            acc[i][j] = 0.0f;

    const float* Aptr = A + (size_t)m0 * K;
    const float* Bptr = Bm + (size_t)n0 * K;

    for (int k0 = 0; k0 < K; k0 += BK) {
        // Load A tile (transpose into smem)
        #pragma unroll
        for (int r = 0; r < BM; r += 64) {
            float4 v = *reinterpret_cast<const float4*>(
                &Aptr[(size_t)(ldRow + r) * K + k0 + ldC]);
            As[ldC + 0][ldRow + r] = v.x;
            As[ldC + 1][ldRow + r] = v.y;
            As[ldC + 2][ldRow + r] = v.z;
            As[ldC + 3][ldRow + r] = v.w;
        }
        // Load B tile (same pattern)
        #pragma unroll
        for (int r = 0; r < BN; r += 64) {
            float4 v = *reinterpret_cast<const float4*>(
                &Bptr[(size_t)(ldRow + r) * K + k0 + ldC]);
            Bs[ldC + 0][ldRow + r] = v.x;
            Bs[ldC + 1][ldRow + r] = v.y;
            Bs[ldC + 2][ldRow + r] = v.z;
            Bs[ldC + 3][ldRow + r] = v.w;
        }
        __syncthreads();

        #pragma unroll
        for (int k = 0; k < BK; k++) {
            float ra[TM], rb[TN];
            #pragma unroll
            for (int i = 0; i < TM; i += 4) {
                float4 v = *reinterpret_cast<const float4*>(&As[k][trow * TM + i]);
                ra[i + 0] = v.x; ra[i + 1] = v.y; ra[i + 2] = v.z; ra[i + 3] = v.w;
            }
            #pragma unroll
            for (int j = 0; j < TN; j += 4) {
                float4 v = *reinterpret_cast<const float4*>(&Bs[k][tcol * TN + j]);
                rb[j + 0] = v.x; rb[j + 1] = v.y; rb[j + 2] = v.z; rb[j + 3] = v.w;
            }
            #pragma unroll
            for (int i = 0; i < TM; i++)
                #pragma unroll
                for (int j = 0; j < TN; j++)
                    acc[i][j] = fmaf(ra[i], rb[j], acc[i][j]);
        }
        __syncthreads();
    }

    // Write back (float4)
    #pragma unroll
    for (int i = 0; i < TM; i++) {
        const int m = m0 + trow * TM + i;
        float* crow = C + (size_t)m * N + n0 + tcol * TN;
        #pragma unroll
        for (int j = 0; j < TN; j += 4) {
            float4 v;
            v.x = acc[i][j + 0]; v.y = acc[i][j + 1];
            v.z = acc[i][j + 2]; v.w = acc[i][j + 3];
            *reinterpret_cast<float4*>(&crow[j]) = v;
        }
    }
}

// ----------------------------------------------------------------------------
// LIF scan: sequential over T, one thread per (b,h) lane. Coalesced on the
// fast (b*H + h) axis. Matches reference fp ops exactly:
//   h = v + (x - v) * 0.5  (TAU=2.0, /2 == *0.5 exactly)
//   s = (h >= 1) ; v = s ? 0 : h
// ----------------------------------------------------------------------------
__global__ void __launch_bounds__(256)
lif_scan(const float* __restrict__ xp, float* __restrict__ spk)
{
    const int idx = blockIdx.x * blockDim.x + threadIdx.x;
    const int BH = B_DIM * H_DIM;
    if (idx >= BH) return;

    float v = 0.0f;
    #pragma unroll 4
    for (int t = 0; t < T_DIM; t++) {
        const float x = xp[(size_t)t * BH + idx];
        const float h = v + (x - v) * 0.5f;
        const bool fire = (h >= 1.0f);
        spk[(size_t)t * BH + idx] = fire ? 1.0f : 0.0f;
        v = fire ? 0.0f : h;
    }
}

// ----------------------------------------------------------------------------
// Launch
// ----------------------------------------------------------------------------
extern "C" void kernel_launch(void* const* d_in, const int* in_sizes, int n_in,
                              void* d_out, int out_size)
{
    const float* x  = (const float*)d_in[0];  // [T,B,H]
    const float* W1 = (const float*)d_in[1];  // [H,H] (out,in)
    const float* W2 = (const float*)d_in[2];  // [H,H]
    float* out = (float*)d_out;               // [T,B,H]

    float* xp = nullptr;
    float* sp = nullptr;
    cudaGetSymbolAddress((void**)&xp, g_xproj);
    cudaGetSymbolAddress((void**)&sp, g_spk);

    constexpr int BM = 128, BN = 128, BK = 16, TM = 8, TN = 8;
    dim3 grid(H_DIM / BN, M_DIM / BM);  // (8, 64)
    dim3 block(256);

    // GEMM1: x_proj = x @ W1^T
    sgemm_nt<BM, BN, BK, TM, TN><<<grid, block>>>(x, W1, xp, M_DIM, H_DIM, H_DIM);

    // LIF scan
    const int BH = B_DIM * H_DIM;
    lif_scan<<<(BH + 255) / 256, 256>>>(xp, sp);

    // GEMM2: out = spikes @ W2^T
    sgemm_nt<BM, BN, BK, TM, TN><<<grid, block>>>(sp, W2, out, M_DIM, H_DIM, H_DIM);
}

// round 3
// speedup vs baseline: 1.5681x; 1.5681x over previous
#include <cuda_runtime.h>
#include <cstdint>

// Problem dims (fixed by the dataset)
#define T_DIM 128
#define B_DIM 64
#define H_DIM 1024
#define M_DIM (T_DIM * B_DIM)   // 8192 rows for both GEMMs

// Scratch (allocation-free rule: __device__ globals)
__device__ float g_xproj[(size_t)M_DIM * H_DIM];  // 32 MB
__device__ float g_spk[(size_t)M_DIM * H_DIM];    // 32 MB
__device__ float g_w2t[(size_t)H_DIM * H_DIM];    // 4 MB (tf32-rounded W2)

// ============================================================================
// Helpers
// ============================================================================
__device__ __forceinline__ uint32_t smem_u32(const void* p) {
    uint32_t a;
    asm("{ .reg .u64 t; cvta.to.shared.u64 t, %1; cvt.u32.u64 %0, t; }"
        : "=r"(a) : "l"(p));
    return a;
}

__device__ __forceinline__ void cp_async16(uint32_t dst, const void* src) {
    asm volatile("cp.async.cg.shared.global [%0], [%1], 16;"
                 :: "r"(dst), "l"(src) : "memory");
}
#define CP_ASYNC_COMMIT() asm volatile("cp.async.commit_group;" ::: "memory")
#define CP_ASYNC_WAIT(n)  asm volatile("cp.async.wait_group %0;" :: "n"(n) : "memory")

// m16n8k8 TF32 MMA (row-major A, col-major B), fp32 accumulate.
__device__ __forceinline__ void mma_tf32(float* d, const uint32_t* a, const uint32_t* b) {
    asm volatile(
        "mma.sync.aligned.m16n8k8.row.col.f32.tf32.tf32.f32 "
        "{%0,%1,%2,%3}, {%4,%5,%6,%7}, {%8,%9}, {%0,%1,%2,%3};"
        : "+f"(d[0]), "+f"(d[1]), "+f"(d[2]), "+f"(d[3])
        : "r"(a[0]), "r"(a[1]), "r"(a[2]), "r"(a[3]),
          "r"(b[0]), "r"(b[1]));
}

// ============================================================================
// TF32 tensor-core NT-GEMM: C[M,N] = A[M,K] * B[N,K]^T (both K-major fp32).
// CTA tile 128x128, BK=32, 256 threads (8 warps: 2(M) x 4(N) of 64x32).
// cp.async double-buffered smem; XOR swizzle for conflict-free STS/LDS.
// Smem layout per operand tile (128 rows x 32 floats):
//   float index = row*32 + (((k>>2) ^ (row&7)) << 2) + (k&3)
// ============================================================================
#define BKF       32                       // K per stage (floats)
#define TILE_U32  (128 * BKF)              // 4096 u32 = 16 KB
#define STAGE_BYTES (2 * TILE_U32 * 4)     // A + B = 32 KB
#define SMEM_DYN  (2 * STAGE_BYTES)        // double buffer = 64 KB

__global__ void __launch_bounds__(256, 1)
gemm_tf32_mma(const float* __restrict__ A,   // [M, K=1024]
              const float* __restrict__ Bm,  // [N=1024, K=1024]
              float* __restrict__ C)         // [M, N=1024]
{
    extern __shared__ float sm[];
    const uint32_t smu = smem_u32(sm);

    const int tid  = threadIdx.x;
    const int wid  = tid >> 5;
    const int lane = tid & 31;
    const int g = lane >> 2;      // group id (0..7)
    const int t = lane & 3;       // thread-in-group (0..3)
    const int wm = (wid >> 2) * 64;   // warp M offset within CTA tile
    const int wn = (wid & 3) * 32;    // warp N offset

    const int m0 = blockIdx.y * 128;
    const int n0 = blockIdx.x * 128;

    const float* Abase = A  + (size_t)m0 * H_DIM;
    const float* Bbase = Bm + (size_t)n0 * H_DIM;

    // Per-thread cp.async geometry: 1024 float4 per operand tile / 256 thr = 4.
    int ldr[4], ldq[4];
    uint32_t sdst[4];
#pragma unroll
    for (int p = 0; p < 4; p++) {
        int f = tid + p * 256;
        ldr[p] = f >> 3;          // row 0..127
        ldq[p] = f & 7;           // 16B chunk 0..7
        sdst[p] = (uint32_t)((ldr[p] * 32 + ((ldq[p] ^ (ldr[p] & 7)) << 2)) * 4);
    }

    float acc[4][4][4];
#pragma unroll
    for (int i = 0; i < 4; i++)
#pragma unroll
        for (int j = 0; j < 4; j++)
#pragma unroll
            for (int r = 0; r < 4; r++) acc[i][j][r] = 0.0f;

    // ---- prefetch helper (macro-ish lambda) ----
    auto prefetch = [&](int chunk, int buf) {
        const uint32_t base = smu + (uint32_t)buf * STAGE_BYTES;
#pragma unroll
        for (int p = 0; p < 4; p++) {
            const float* sa = Abase + (size_t)ldr[p] * H_DIM + chunk * BKF + ldq[p] * 4;
            cp_async16(base + sdst[p], sa);
        }
#pragma unroll
        for (int p = 0; p < 4; p++) {
            const float* sb = Bbase + (size_t)ldr[p] * H_DIM + chunk * BKF + ldq[p] * 4;
            cp_async16(base + (uint32_t)TILE_U32 * 4 + sdst[p], sb);
        }
    };

    const int NCH = H_DIM / BKF;  // 32
    prefetch(0, 0);
    CP_ASYNC_COMMIT();

    int buf = 0;
    for (int it = 0; it < NCH; ++it) {
        if (it + 1 < NCH) {
            prefetch(it + 1, buf ^ 1);
            CP_ASYNC_COMMIT();
            CP_ASYNC_WAIT(1);
        } else {
            CP_ASYNC_WAIT(0);
        }
        __syncthreads();

        const uint32_t* As = (const uint32_t*)sm + (size_t)buf * (2 * TILE_U32);
        const uint32_t* Bs = As + TILE_U32;

#pragma unroll
        for (int ks = 0; ks < 4; ks++) {
            const int c0 = ((ks * 2) ^ g) << 2;       // swizzled 16B chunk, k in [ks*8, ks*8+4)
            const int c1 = ((ks * 2 + 1) ^ g) << 2;   // k in [ks*8+4, ks*8+8)

            uint32_t af[4][4];
#pragma unroll
            for (int mt = 0; mt < 4; mt++) {
                const int mb = wm + mt * 16 + g;
                af[mt][0] = As[mb * 32 + c0 + t];
                af[mt][1] = As[(mb + 8) * 32 + c0 + t];
                af[mt][2] = As[mb * 32 + c1 + t];
                af[mt][3] = As[(mb + 8) * 32 + c1 + t];
            }
            uint32_t bf[4][2];
#pragma unroll
            for (int nt = 0; nt < 4; nt++) {
                const int nb = wn + nt * 8 + g;
                bf[nt][0] = Bs[nb * 32 + c0 + t];
                bf[nt][1] = Bs[nb * 32 + c1 + t];
            }
#pragma unroll
            for (int mt = 0; mt < 4; mt++)
#pragma unroll
                for (int nt = 0; nt < 4; nt++)
                    mma_tf32(acc[mt][nt], af[mt], bf[nt]);
        }
        __syncthreads();
        buf ^= 1;
    }

    // Epilogue: direct STG (float2 pairs; fragment cols 2t, 2t+1 contiguous)
#pragma unroll
    for (int mt = 0; mt < 4; mt++) {
#pragma unroll
        for (int nt = 0; nt < 4; nt++) {
            const int row = m0 + wm + mt * 16 + g;
            const int col = n0 + wn + nt * 8 + 2 * t;
            float2 v01 = make_float2(acc[mt][nt][0], acc[mt][nt][1]);
            float2 v23 = make_float2(acc[mt][nt][2], acc[mt][nt][3]);
            *(float2*)&C[(size_t)row * H_DIM + col] = v01;
            *(float2*)&C[(size_t)(row + 8) * H_DIM + col] = v23;
        }
    }
}

// ----------------------------------------------------------------------------
// Round W2 to TF32 (rna) once, so mma operand error = proper tf32 rounding.
// ----------------------------------------------------------------------------
__global__ void __launch_bounds__(256)
round_w2_tf32(const float* __restrict__ W, float* __restrict__ Wt)
{
    int i = (blockIdx.x * blockDim.x + threadIdx.x) * 4;
    float4 v = *(const float4*)(W + i);
    uint32_t o0, o1, o2, o3;
    asm("cvt.rna.tf32.f32 %0, %1;" : "=r"(o0) : "f"(v.x));
    asm("cvt.rna.tf32.f32 %0, %1;" : "=r"(o1) : "f"(v.y));
    asm("cvt.rna.tf32.f32 %0, %1;" : "=r"(o2) : "f"(v.z));
    asm("cvt.rna.tf32.f32 %0, %1;" : "=r"(o3) : "f"(v.w));
    float4 r;
    r.x = __uint_as_float(o0); r.y = __uint_as_float(o1);
    r.z = __uint_as_float(o2); r.w = __uint_as_float(o3);
    *(float4*)(Wt + i) = r;
}

// ----------------------------------------------------------------------------
// Exact-fp32 SIMT SGEMM (GEMM1 — feeds the spike threshold, must stay fp32)
// ----------------------------------------------------------------------------
template<int BM, int BN, int BKT, int TM, int TN>
__global__ void __launch_bounds__(256, 1)
sgemm_nt(const float* __restrict__ A,
         const float* __restrict__ Bm,
         float* __restrict__ C,
         int M, int N, int K)
{
    __shared__ float As[BKT][BM];
    __shared__ float Bs[BKT][BN];

    const int tid  = threadIdx.x;
    const int tcol = tid % (BN / TN);
    const int trow = tid / (BN / TN);
    const int m0 = blockIdx.y * BM;
    const int n0 = blockIdx.x * BN;

    const int ldRow = tid / (BKT / 4);
    const int ldC   = (tid % (BKT / 4)) * 4;

    float acc[TM][TN];
    #pragma unroll
    for (int i = 0; i < TM; i++)
        #pragma unroll
        for (int j = 0; j < TN; j++)
            acc[i][j] = 0.0f;

    const float* Aptr = A + (size_t)m0 * K;
    const float* Bptr = Bm + (size_t)n0 * K;

    for (int k0 = 0; k0 < K; k0 += BKT) {
        #pragma unroll
        for (int r = 0; r < BM; r += 64) {
            float4 v = *reinterpret_cast<const float4*>(
                &Aptr[(size_t)(ldRow + r) * K + k0 + ldC]);
            As[ldC + 0][ldRow + r] = v.x;
            As[ldC + 1][ldRow + r] = v.y;
            As[ldC + 2][ldRow + r] = v.z;
            As[ldC + 3][ldRow + r] = v.w;
        }
        #pragma unroll
        for (int r = 0; r < BN; r += 64) {
            float4 v = *reinterpret_cast<const float4*>(
                &Bptr[(size_t)(ldRow + r) * K + k0 + ldC]);
            Bs[ldC + 0][ldRow + r] = v.x;
            Bs[ldC + 1][ldRow + r] = v.y;
            Bs[ldC + 2][ldRow + r] = v.z;
            Bs[ldC + 3][ldRow + r] = v.w;
        }
        __syncthreads();

        #pragma unroll
        for (int k = 0; k < BKT; k++) {
            float ra[TM], rb[TN];
            #pragma unroll
            for (int i = 0; i < TM; i += 4) {
                float4 v = *reinterpret_cast<const float4*>(&As[k][trow * TM + i]);
                ra[i + 0] = v.x; ra[i + 1] = v.y; ra[i + 2] = v.z; ra[i + 3] = v.w;
            }
            #pragma unroll
            for (int j = 0; j < TN; j += 4) {
                float4 v = *reinterpret_cast<const float4*>(&Bs[k][tcol * TN + j]);
                rb[j + 0] = v.x; rb[j + 1] = v.y; rb[j + 2] = v.z; rb[j + 3] = v.w;
            }
            #pragma unroll
            for (int i = 0; i < TM; i++)
                #pragma unroll
                for (int j = 0; j < TN; j++)
                    acc[i][j] = fmaf(ra[i], rb[j], acc[i][j]);
        }
        __syncthreads();
    }

    #pragma unroll
    for (int i = 0; i < TM; i++) {
        const int m = m0 + trow * TM + i;
        float* crow = C + (size_t)m * N + n0 + tcol * TN;
        #pragma unroll
        for (int j = 0; j < TN; j += 4) {
            float4 v;
            v.x = acc[i][j + 0]; v.y = acc[i][j + 1];
            v.z = acc[i][j + 2]; v.w = acc[i][j + 3];
            *reinterpret_cast<float4*>(&crow[j]) = v;
        }
    }
}

// ----------------------------------------------------------------------------
// LIF scan (exact fp ops vs reference)
// ----------------------------------------------------------------------------
__global__ void __launch_bounds__(256)
lif_scan(const float* __restrict__ xp, float* __restrict__ spk)
{
    const int idx = blockIdx.x * blockDim.x + threadIdx.x;
    const int BH = B_DIM * H_DIM;
    if (idx >= BH) return;

    float v = 0.0f;
    #pragma unroll 4
    for (int t = 0; t < T_DIM; t++) {
        const float x = xp[(size_t)t * BH + idx];
        const float h = v + (x - v) * 0.5f;
        const bool fire = (h >= 1.0f);
        spk[(size_t)t * BH + idx] = fire ? 1.0f : 0.0f;
        v = fire ? 0.0f : h;
    }
}

// ----------------------------------------------------------------------------
// Launch
// ----------------------------------------------------------------------------
extern "C" void kernel_launch(void* const* d_in, const int* in_sizes, int n_in,
                              void* d_out, int out_size)
{
    const float* x  = (const float*)d_in[0];  // [T,B,H]
    const float* W1 = (const float*)d_in[1];  // [H,H] (out,in)
    const float* W2 = (const float*)d_in[2];  // [H,H]
    float* out = (float*)d_out;               // [T,B,H]

    float* xp = nullptr;
    float* sp = nullptr;
    float* w2t = nullptr;
    cudaGetSymbolAddress((void**)&xp, g_xproj);
    cudaGetSymbolAddress((void**)&sp, g_spk);
    cudaGetSymbolAddress((void**)&w2t, g_w2t);

    // GEMM1 (exact fp32): x_proj = x @ W1^T
    {
        constexpr int BM = 128, BN = 128, BKT = 16, TM = 8, TN = 8;
        dim3 grid(H_DIM / BN, M_DIM / BM);
        sgemm_nt<BM, BN, BKT, TM, TN><<<grid, 256>>>(x, W1, xp, M_DIM, H_DIM, H_DIM);
    }

    // LIF scan
    const int BH = B_DIM * H_DIM;
    lif_scan<<<(BH + 255) / 256, 256>>>(xp, sp);

    // Pre-round W2 to tf32 (rna)
    round_w2_tf32<<<(H_DIM * H_DIM) / (256 * 4), 256>>>(W2, w2t);

    // GEMM2 (mma.sync tf32): out = spikes @ W2^T
    cudaFuncSetAttribute(gemm_tf32_mma,
                         cudaFuncAttributeMaxDynamicSharedMemorySize, SMEM_DYN);
    dim3 grid2(H_DIM / 128, M_DIM / 128);  // (8, 64)
    gemm_tf32_mma<<<grid2, 256, SMEM_DYN>>>(sp, w2t, out);
}

// round 5
// speedup vs baseline: 2.3812x; 1.5185x over previous
#include <cuda_runtime.h>
#include <cstdint>

// Problem dims (fixed by the dataset)
#define T_DIM 128
#define B_DIM 64
#define H_DIM 1024
#define M_DIM (T_DIM * B_DIM)   // 8192
#define BH    (B_DIM * H_DIM)   // 65536

// Scratch (allocation-free rule: __device__ globals)
__device__ float g_xt[(size_t)M_DIM * H_DIM];     // 32 MB  tf32-rounded x
__device__ float g_xproj[(size_t)M_DIM * H_DIM];  // 32 MB  approx x_proj
__device__ float g_spk[(size_t)M_DIM * H_DIM];    // 32 MB  spikes
__device__ float g_w1t[(size_t)H_DIM * H_DIM];    // 4 MB   tf32-rounded W1
__device__ float g_w2t[(size_t)H_DIM * H_DIM];    // 4 MB   tf32-rounded W2
__device__ int   g_cnt[B_DIM];                    // flagged count per b
__device__ int   g_list[B_DIM * H_DIM];           // flagged h list per b

#define DELTA 3e-3f

// ============================================================================
// Helpers
// ============================================================================
__device__ __forceinline__ uint32_t smem_u32(const void* p) {
    uint32_t a;
    asm("{ .reg .u64 t; cvta.to.shared.u64 t, %1; cvt.u32.u64 %0, t; }"
        : "=r"(a) : "l"(p));
    return a;
}
__device__ __forceinline__ void cp_async16(uint32_t dst, const void* src) {
    asm volatile("cp.async.cg.shared.global [%0], [%1], 16;"
                 :: "r"(dst), "l"(src) : "memory");
}
#define CP_ASYNC_COMMIT() asm volatile("cp.async.commit_group;" ::: "memory")
#define CP_ASYNC_WAIT(n)  asm volatile("cp.async.wait_group %0;" :: "n"(n) : "memory")

__device__ __forceinline__ void mma_tf32(float* d, const uint32_t* a, const uint32_t* b) {
    asm volatile(
        "mma.sync.aligned.m16n8k8.row.col.f32.tf32.tf32.f32 "
        "{%0,%1,%2,%3}, {%4,%5,%6,%7}, {%8,%9}, {%0,%1,%2,%3};"
        : "+f"(d[0]), "+f"(d[1]), "+f"(d[2]), "+f"(d[3])
        : "r"(a[0]), "r"(a[1]), "r"(a[2]), "r"(a[3]),
          "r"(b[0]), "r"(b[1]));
}

// ============================================================================
// Plain TF32 tensor-core NT-GEMM (validated in R3):
// C[M,N] = A[M,K] * B[N,K]^T, operands pre-rounded to tf32 values.
// CTA tile 128x128, BK=32, 256 threads, cp.async double buffer, XOR swizzle.
// ============================================================================
#define BKF       32
#define TILE_U32  (128 * BKF)              // 4096 u32 = 16 KB
#define STAGE_BYTES (2 * TILE_U32 * 4)     // 32 KB
#define SMEM_DYN  (2 * STAGE_BYTES)        // 64 KB

__global__ void __launch_bounds__(256, 1)
gemm_tf32_mma(const float* __restrict__ A,
              const float* __restrict__ Bm,
              float* __restrict__ C)
{
    extern __shared__ float sm[];
    const uint32_t smu = smem_u32(sm);

    const int tid  = threadIdx.x;
    const int wid  = tid >> 5;
    const int lane = tid & 31;
    const int g = lane >> 2;
    const int t = lane & 3;
    const int wm = (wid >> 2) * 64;
    const int wn = (wid & 3) * 32;

    const int m0 = blockIdx.y * 128;
    const int n0 = blockIdx.x * 128;

    const float* Abase = A  + (size_t)m0 * H_DIM;
    const float* Bbase = Bm + (size_t)n0 * H_DIM;

    int ldr[4], ldq[4];
    uint32_t sdst[4];
#pragma unroll
    for (int p = 0; p < 4; p++) {
        int f = tid + p * 256;
        ldr[p] = f >> 3;
        ldq[p] = f & 7;
        sdst[p] = (uint32_t)((ldr[p] * 32 + ((ldq[p] ^ (ldr[p] & 7)) << 2)) * 4);
    }

    float acc[4][4][4];
#pragma unroll
    for (int i = 0; i < 4; i++)
#pragma unroll
        for (int j = 0; j < 4; j++)
#pragma unroll
            for (int r = 0; r < 4; r++) acc[i][j][r] = 0.0f;

    auto prefetch = [&](int chunk, int buf) {
        const uint32_t base = smu + (uint32_t)buf * STAGE_BYTES;
#pragma unroll
        for (int p = 0; p < 4; p++)
            cp_async16(base + sdst[p],
                       Abase + (size_t)ldr[p] * H_DIM + chunk * BKF + ldq[p] * 4);
#pragma unroll
        for (int p = 0; p < 4; p++)
            cp_async16(base + (uint32_t)TILE_U32 * 4 + sdst[p],
                       Bbase + (size_t)ldr[p] * H_DIM + chunk * BKF + ldq[p] * 4);
    };

    const int NCH = H_DIM / BKF;
    prefetch(0, 0);
    CP_ASYNC_COMMIT();

    int buf = 0;
    for (int it = 0; it < NCH; ++it) {
        if (it + 1 < NCH) {
            prefetch(it + 1, buf ^ 1);
            CP_ASYNC_COMMIT();
            CP_ASYNC_WAIT(1);
        } else {
            CP_ASYNC_WAIT(0);
        }
        __syncthreads();

        const uint32_t* As = (const uint32_t*)sm + (size_t)buf * (2 * TILE_U32);
        const uint32_t* Bs = As + TILE_U32;

#pragma unroll
        for (int ks = 0; ks < 4; ks++) {
            const int c0 = ((ks * 2) ^ g) << 2;
            const int c1 = ((ks * 2 + 1) ^ g) << 2;

            uint32_t af[4][4];
#pragma unroll
            for (int mt = 0; mt < 4; mt++) {
                const int mb = wm + mt * 16 + g;
                af[mt][0] = As[mb * 32 + c0 + t];
                af[mt][1] = As[(mb + 8) * 32 + c0 + t];
                af[mt][2] = As[mb * 32 + c1 + t];
                af[mt][3] = As[(mb + 8) * 32 + c1 + t];
            }
            uint32_t bf[4][2];
#pragma unroll
            for (int nt = 0; nt < 4; nt++) {
                const int nb = wn + nt * 8 + g;
                bf[nt][0] = Bs[nb * 32 + c0 + t];
                bf[nt][1] = Bs[nb * 32 + c1 + t];
            }
#pragma unroll
            for (int mt = 0; mt < 4; mt++)
#pragma unroll
                for (int nt = 0; nt < 4; nt++)
                    mma_tf32(acc[mt][nt], af[mt], bf[nt]);
        }
        __syncthreads();
        buf ^= 1;
    }

#pragma unroll
    for (int mt = 0; mt < 4; mt++) {
#pragma unroll
        for (int nt = 0; nt < 4; nt++) {
            const int row = m0 + wm + mt * 16 + g;
            const int col = n0 + wn + nt * 8 + 2 * t;
            float2 v01 = make_float2(acc[mt][nt][0], acc[mt][nt][1]);
            float2 v23 = make_float2(acc[mt][nt][2], acc[mt][nt][3]);
            *(float2*)&C[(size_t)row * H_DIM + col] = v01;
            *(float2*)&C[(size_t)(row + 8) * H_DIM + col] = v23;
        }
    }
}

// ----------------------------------------------------------------------------
// Round fp32 array to TF32 values (rna), float4 per thread.
// ----------------------------------------------------------------------------
__global__ void __launch_bounds__(256)
round_tf32(const float* __restrict__ src, float* __restrict__ dst)
{
    int i = (blockIdx.x * blockDim.x + threadIdx.x) * 4;
    float4 v = *(const float4*)(src + i);
    uint32_t o0, o1, o2, o3;
    asm("cvt.rna.tf32.f32 %0, %1;" : "=r"(o0) : "f"(v.x));
    asm("cvt.rna.tf32.f32 %0, %1;" : "=r"(o1) : "f"(v.y));
    asm("cvt.rna.tf32.f32 %0, %1;" : "=r"(o2) : "f"(v.z));
    asm("cvt.rna.tf32.f32 %0, %1;" : "=r"(o3) : "f"(v.w));
    float4 r;
    r.x = __uint_as_float(o0); r.y = __uint_as_float(o1);
    r.z = __uint_as_float(o2); r.w = __uint_as_float(o3);
    *(float4*)(dst + i) = r;
}

// ----------------------------------------------------------------------------
// LIF scan over approx x_proj + flag threshold-marginal lanes.
// ----------------------------------------------------------------------------
__global__ void __launch_bounds__(256)
scan_flag(const float* __restrict__ xp, float* __restrict__ spk,
          int* __restrict__ cnt, int* __restrict__ list)
{
    const int idx = blockIdx.x * blockDim.x + threadIdx.x;
    if (idx >= BH) return;

    float v = 0.0f;
    bool flag = false;
    #pragma unroll 4
    for (int t = 0; t < T_DIM; t++) {
        const float x = xp[(size_t)t * BH + idx];
        const float h = v + (x - v) * 0.5f;
        flag |= (fabsf(h - 1.0f) < DELTA);
        const bool fire = (h >= 1.0f);
        spk[(size_t)t * BH + idx] = fire ? 1.0f : 0.0f;
        v = fire ? 0.0f : h;
    }
    if (flag) {
        const int b = idx >> 10;
        const int h = idx & 1023;
        int p = atomicAdd(&cnt[b], 1);
        list[(b << 10) + p] = h;
    }
}

// ----------------------------------------------------------------------------
// Fixup: for flagged lanes, recompute x_proj column in EXACT sequential fp32
// (thread-private full-K accumulation), then rerun LIF and overwrite spikes.
// Grid: (64 b, 8 slices), 256 threads. Batch of up to 32 h's at a time.
//   Xs: x[t, b, kc*64 .. +64)  staged in smem (stride 65, conflict-free)
//   Ws: W1 rows for batch h's  staged in smem
//   thread owns 4(j) x 4(t) pairs, t strided by 32 -> conflict-free LDS
// ----------------------------------------------------------------------------
__global__ void __launch_bounds__(256)
fixup_scan(const float* __restrict__ x,   // original fp32 x [T,B,H]
           const float* __restrict__ W1,  // original fp32 W1 [H,H]
           const int* __restrict__ cnt,
           const int* __restrict__ list,
           float* __restrict__ spk)
{
    __shared__ float Xs[128 * 65];   // 33280 B
    __shared__ float Ws[32 * 64];    //  8192 B
    __shared__ int   hlist[32];

    const int b     = blockIdx.x;
    const int slice = blockIdx.y;       // 0..7
    const int tid   = threadIdx.x;
    const int lane  = tid & 31;
    const int jb    = tid >> 5;         // warp id = j-block (0..7 -> 4 j each... see map)
    const int n     = cnt[b];

    // j mapping: thread owns j in {jb*4 .. jb*4+3}? 8 warps x 4 = 32 j ✓
    // t mapping: t = lane + tt*32, tt = 0..3  -> 128 t ✓
    for (int base = slice * 32; base < n; base += 8 * 32) {
        const int nh = min(32, n - base);

        if (tid < 32)
            hlist[tid] = (base + tid < n) ? list[(b << 10) + base + tid] : 0;
        __syncthreads();

        float acc[4][4];
#pragma unroll
        for (int jj = 0; jj < 4; jj++)
#pragma unroll
            for (int tt = 0; tt < 4; tt++) acc[jj][tt] = 0.0f;

        for (int kc = 0; kc < 16; kc++) {
            // stage Xs: 128 t x 64 k  (2048 float4, 8 per thread)
#pragma unroll
            for (int p = 0; p < 8; p++) {
                int f = tid + p * 256;
                int tt_ = f >> 4, c4 = f & 15;
                float4 v = *(const float4*)(x + (size_t)tt_ * BH + (b << 10) + kc * 64 + c4 * 4);
                float* d = &Xs[tt_ * 65 + c4 * 4];
                d[0] = v.x; d[1] = v.y; d[2] = v.z; d[3] = v.w;
            }
            // stage Ws: 32 j x 64 k (512 float4, 2 per thread)
#pragma unroll
            for (int p = 0; p < 2; p++) {
                int f = tid + p * 256;
                int j = f >> 4, c4 = f & 15;
                float4 v = *(const float4*)(W1 + (size_t)hlist[j] * H_DIM + kc * 64 + c4 * 4);
                *(float4*)&Ws[j * 64 + c4 * 4] = v;
            }
            __syncthreads();

            // accumulate: exact fp32, thread-sequential over k
            for (int k = 0; k < 64; k++) {
                float wv[4], xv[4];
#pragma unroll
                for (int jj = 0; jj < 4; jj++) wv[jj] = Ws[(jb * 4 + jj) * 64 + k];
#pragma unroll
                for (int tt = 0; tt < 4; tt++) xv[tt] = Xs[(lane + tt * 32) * 65 + k];
#pragma unroll
                for (int jj = 0; jj < 4; jj++)
#pragma unroll
                    for (int tt = 0; tt < 4; tt++)
                        acc[jj][tt] = fmaf(wv[jj], xv[tt], acc[jj][tt]);
            }
            __syncthreads();
        }

        // write xcol into smem (alias Xs region): xcol[j*129 + t]
        float* xcol = Xs;
#pragma unroll
        for (int jj = 0; jj < 4; jj++)
#pragma unroll
            for (int tt = 0; tt < 4; tt++)
                xcol[(jb * 4 + jj) * 129 + lane + tt * 32] = acc[jj][tt];
        __syncthreads();

        // LIF rerun for this batch (threads 0..31, one per j)
        if (tid < nh) {
            const int h = hlist[tid];
            float v = 0.0f;
            for (int t = 0; t < T_DIM; t++) {
                const float xc = xcol[tid * 129 + t];
                const float hm = v + (xc - v) * 0.5f;
                const bool fire = (hm >= 1.0f);
                spk[(size_t)t * BH + (b << 10) + h] = fire ? 1.0f : 0.0f;
                v = fire ? 0.0f : hm;
            }
        }
        __syncthreads();
    }
}

// ----------------------------------------------------------------------------
// Launch
// ----------------------------------------------------------------------------
extern "C" void kernel_launch(void* const* d_in, const int* in_sizes, int n_in,
                              void* d_out, int out_size)
{
    const float* x  = (const float*)d_in[0];  // [T,B,H]
    const float* W1 = (const float*)d_in[1];  // [H,H]
    const float* W2 = (const float*)d_in[2];  // [H,H]
    float* out = (float*)d_out;               // [T,B,H]

    float *xt, *xp, *sp, *w1t, *w2t;
    int *cnt, *list;
    cudaGetSymbolAddress((void**)&xt, g_xt);
    cudaGetSymbolAddress((void**)&xp, g_xproj);
    cudaGetSymbolAddress((void**)&sp, g_spk);
    cudaGetSymbolAddress((void**)&w1t, g_w1t);
    cudaGetSymbolAddress((void**)&w2t, g_w2t);
    cudaGetSymbolAddress((void**)&cnt, g_cnt);
    cudaGetSymbolAddress((void**)&list, g_list);

    cudaFuncSetAttribute(gemm_tf32_mma,
                         cudaFuncAttributeMaxDynamicSharedMemorySize, SMEM_DYN);

    // zero flag counters
    cudaMemsetAsync(cnt, 0, B_DIM * sizeof(int));

    // tf32-round operands (rna, unbiased)
    round_tf32<<<(M_DIM * H_DIM) / (256 * 4), 256>>>(x, xt);
    round_tf32<<<(H_DIM * H_DIM) / (256 * 4), 256>>>(W1, w1t);
    round_tf32<<<(H_DIM * H_DIM) / (256 * 4), 256>>>(W2, w2t);

    dim3 grid(H_DIM / 128, M_DIM / 128);  // (8, 64)

    // GEMM1 approx (tf32): x_proj ~= x @ W1^T
    gemm_tf32_mma<<<grid, 256, SMEM_DYN>>>(xt, w1t, xp);

    // LIF scan + flag marginal lanes
    scan_flag<<<BH / 256, 256>>>(xp, sp, cnt, list);

    // Exact fp32 fixup + re-scan of flagged lanes
    fixup_scan<<<dim3(B_DIM, 8), 256>>>(x, W1, cnt, list, sp);

    // GEMM2 (tf32): out = spikes @ W2^T
    gemm_tf32_mma<<<grid, 256, SMEM_DYN>>>(sp, w2t, out);
}